// round 1
// baseline (speedup 1.0000x reference)
#include <cuda_runtime.h>

#define NNODES 50000
#define NGRAPH 64
#define FIN    128      // inner K for both GEMMs (F_IN = 2*HID = 128)
#define NCLS   10

// ---------------- scratch (static device arrays; no runtime alloc) ----------
__device__ float g_xlr1[NNODES * 256];   // conv1: [xl(128) | xr(128)]
__device__ float g_agg1[NNODES * 128];   // conv1 weighted sums
__device__ float g_den1[NNODES * 2];     // conv1 softmax denominators (2 heads)
__device__ float g_h1  [NNODES * 128];   // conv1 output (post-ELU)
__device__ float g_xlr2[NNODES * 128];   // conv2: [xl(64) | xr(64)]
__device__ float g_agg2[NNODES * 64];
__device__ float g_den2[NNODES];
__device__ float g_pool[NGRAPH * 64];
__device__ float g_cnt [NGRAPH];
__device__ int   g_idx64;                // 1 if edge_index/batch are int64

// ---------------- helpers ----------------------------------------------------
__device__ __forceinline__ void red_add4(float* p, float4 v) {
    asm volatile("red.global.add.v4.f32 [%0], {%1,%2,%3,%4};"
                 :: "l"(p), "f"(v.x), "f"(v.y), "f"(v.z), "f"(v.w) : "memory");
}

__device__ __forceinline__ float lrelu(float v) { return v > 0.f ? v : 0.2f * v; }
__device__ __forceinline__ float elu(float v)   { return v > 0.f ? v : expm1f(v); }

__device__ __forceinline__ void load_edge(const void* ei, int E, int w, int& s, int& d) {
    if (g_idx64) {
        const long long* p = (const long long*)ei;
        s = (int)p[w]; d = (int)p[E + w];
    } else {
        const int* p = (const int*)ei;
        s = p[w]; d = p[E + w];
    }
}

// ---------------- dtype detection -------------------------------------------
__global__ void detect_idx_kernel(const void* ei) {
    if (threadIdx.x == 0 && blockIdx.x == 0) {
        const long long* p = (const long long*)ei;
        int ok = 1;
        for (int i = 0; i < 16; i++) {
            long long v = p[i];
            if (v < 0 || v >= NNODES) ok = 0;
        }
        g_idx64 = ok;
    }
}

// ---------------- zero accumulators ------------------------------------------
__global__ void zero_all() {
    long i = ((long)blockIdx.x * blockDim.x + threadIdx.x) << 2;
    float4 z = make_float4(0.f, 0.f, 0.f, 0.f);
    if (i < (long)NNODES * 128) *(float4*)&g_agg1[i] = z;
    if (i < (long)NNODES * 64)  *(float4*)&g_agg2[i] = z;
    if (i < NNODES * 2)         *(float4*)&g_den1[i] = z;
    if (i < NNODES)             *(float4*)&g_den2[i] = z;
    if (i < NGRAPH * 64)        *(float4*)&g_pool[i] = z;
    if (i < NGRAPH)             *(float4*)&g_cnt[i]  = z;
}

// ---------------- dual-weight GEMM: C[M x 2*NHALF] = A[M x 128] @ [WL|WR] ----
// BM=64 BN=64 BK=16, 256 threads, 4x4 microtile per thread.
__global__ void gemm_dual(const float* __restrict__ A,
                          const float* __restrict__ WL,
                          const float* __restrict__ WR,
                          float* __restrict__ C,
                          int M, int NHALF, int NN) {
    __shared__ float As[16][64];
    __shared__ float Bs[16][64];
    const int t  = threadIdx.x;
    const int tx = t & 15, ty = t >> 4;
    const int rowBase = blockIdx.y << 6;
    const int colTile = blockIdx.x << 6;

    const float* W;
    int colBase;
    if (colTile >= NHALF) { W = WR; colBase = colTile - NHALF; }
    else                  { W = WL; colBase = colTile; }

    const int arow = t >> 2, ak4 = (t & 3) << 2;   // A loader: 64 rows x 16 k
    const int brow = t >> 4, bc4 = (t & 15) << 2;  // B loader: 16 k x 64 cols

    float acc[4][4];
    #pragma unroll
    for (int i = 0; i < 4; i++)
        #pragma unroll
        for (int j = 0; j < 4; j++) acc[i][j] = 0.f;

    const int grow = rowBase + arow;
    const bool aval = grow < M;
    const float* Arow = A + (long)grow * FIN;

    for (int k0 = 0; k0 < FIN; k0 += 16) {
        float4 av = aval ? *(const float4*)(Arow + k0 + ak4)
                         : make_float4(0.f, 0.f, 0.f, 0.f);
        As[ak4 + 0][arow] = av.x;
        As[ak4 + 1][arow] = av.y;
        As[ak4 + 2][arow] = av.z;
        As[ak4 + 3][arow] = av.w;
        *(float4*)&Bs[brow][bc4] =
            *(const float4*)(W + (long)(k0 + brow) * NHALF + colBase + bc4);
        __syncthreads();
        #pragma unroll
        for (int k = 0; k < 16; k++) {
            float4 a = *(const float4*)&As[k][ty << 2];
            float4 b = *(const float4*)&Bs[k][tx << 2];
            acc[0][0] += a.x * b.x; acc[0][1] += a.x * b.y;
            acc[0][2] += a.x * b.z; acc[0][3] += a.x * b.w;
            acc[1][0] += a.y * b.x; acc[1][1] += a.y * b.y;
            acc[1][2] += a.y * b.z; acc[1][3] += a.y * b.w;
            acc[2][0] += a.z * b.x; acc[2][1] += a.z * b.y;
            acc[2][2] += a.z * b.z; acc[2][3] += a.z * b.w;
            acc[3][0] += a.w * b.x; acc[3][1] += a.w * b.y;
            acc[3][2] += a.w * b.z; acc[3][3] += a.w * b.w;
        }
        __syncthreads();
    }
    #pragma unroll
    for (int i = 0; i < 4; i++) {
        int r = rowBase + (ty << 2) + i;
        if (r < M) {
            float4 v = make_float4(acc[i][0], acc[i][1], acc[i][2], acc[i][3]);
            *(float4*)&C[(long)r * NN + colTile + (tx << 2)] = v;
        }
    }
}

// ---------------- conv1 edge pass: 1 warp / edge, 2 heads x 64 ch ------------
__global__ void edge1_kernel(const void* __restrict__ ei, int E, int ET,
                             const float* __restrict__ att) {
    int w = (int)(((long)blockIdx.x * blockDim.x + threadIdx.x) >> 5);
    if (w >= ET) return;
    int lane = threadIdx.x & 31;
    int s, d;
    if (w < E) load_edge(ei, E, w, s, d);
    else       s = d = w - E;

    float4 a = *(const float4*)&g_xlr1[(long)s * 256 + (lane << 2)];
    float4 r = *(const float4*)&g_xlr1[(long)d * 256 + 128 + (lane << 2)];
    float4 av = *(const float4*)&att[lane << 2];

    float e = lrelu(a.x + r.x) * av.x + lrelu(a.y + r.y) * av.y +
              lrelu(a.z + r.z) * av.z + lrelu(a.w + r.w) * av.w;
    // reduce within 16-lane head group (lanes 0-15: head0, 16-31: head1)
    e += __shfl_xor_sync(0xffffffffu, e, 8);
    e += __shfl_xor_sync(0xffffffffu, e, 4);
    e += __shfl_xor_sync(0xffffffffu, e, 2);
    e += __shfl_xor_sync(0xffffffffu, e, 1);
    float p = expf(e);

    red_add4(&g_agg1[(long)d * 128 + (lane << 2)],
             make_float4(p * a.x, p * a.y, p * a.z, p * a.w));
    if ((lane & 15) == 0) atomicAdd(&g_den1[d * 2 + (lane >> 4)], p);
}

// ---------------- conv1 node pass: h1 = elu(agg/den + b1) --------------------
__global__ void node1_kernel(const float* __restrict__ b1, int Nn) {
    int idx = blockIdx.x * blockDim.x + threadIdx.x;   // Nn*32 threads
    if (idx >= Nn * 32) return;
    int n = idx >> 5, c4 = (idx & 31) << 2;
    float inv = 1.f / g_den1[n * 2 + (c4 >> 6)];
    float4 g = *(const float4*)&g_agg1[(long)n * 128 + c4];
    float4 b = *(const float4*)&b1[c4];
    float4 h;
    h.x = elu(g.x * inv + b.x);
    h.y = elu(g.y * inv + b.y);
    h.z = elu(g.z * inv + b.z);
    h.w = elu(g.w * inv + b.w);
    *(float4*)&g_h1[(long)n * 128 + c4] = h;
}

// ---------------- conv2 edge pass: 16 lanes / edge, 1 head x 64 ch -----------
__global__ void edge2_kernel(const void* __restrict__ ei, int E, int ET,
                             const float* __restrict__ att) {
    int idx = (int)(((long)blockIdx.x * blockDim.x + threadIdx.x) >> 4);
    if (idx >= ET) return;
    int l = threadIdx.x & 15;
    int s, d;
    if (idx < E) load_edge(ei, E, idx, s, d);
    else         s = d = idx - E;

    float4 a = *(const float4*)&g_xlr2[(long)s * 128 + (l << 2)];
    float4 r = *(const float4*)&g_xlr2[(long)d * 128 + 64 + (l << 2)];
    float4 av = *(const float4*)&att[l << 2];

    float e = lrelu(a.x + r.x) * av.x + lrelu(a.y + r.y) * av.y +
              lrelu(a.z + r.z) * av.z + lrelu(a.w + r.w) * av.w;
    e += __shfl_xor_sync(0xffffffffu, e, 8);
    e += __shfl_xor_sync(0xffffffffu, e, 4);
    e += __shfl_xor_sync(0xffffffffu, e, 2);
    e += __shfl_xor_sync(0xffffffffu, e, 1);
    float p = expf(e);

    red_add4(&g_agg2[(long)d * 64 + (l << 2)],
             make_float4(p * a.x, p * a.y, p * a.z, p * a.w));
    if (l == 0) atomicAdd(&g_den2[d], p);
}

// ---------------- conv2 node pass + pooling ----------------------------------
__global__ void node2_kernel(const float* __restrict__ b2,
                             const void* __restrict__ batch, int Nn) {
    int idx = blockIdx.x * blockDim.x + threadIdx.x;   // Nn*16 threads
    if (idx >= Nn * 16) return;
    int n = idx >> 4, c4 = (idx & 15) << 2;
    float inv = 1.f / g_den2[n];
    float4 g = *(const float4*)&g_agg2[(long)n * 64 + c4];
    float4 b = *(const float4*)&b2[c4];
    float4 h;
    h.x = elu(g.x * inv + b.x);
    h.y = elu(g.y * inv + b.y);
    h.z = elu(g.z * inv + b.z);
    h.w = elu(g.w * inv + b.w);
    int gph = g_idx64 ? (int)((const long long*)batch)[n]
                      : ((const int*)batch)[n];
    red_add4(&g_pool[gph * 64 + c4], h);
    if (c4 == 0) atomicAdd(&g_cnt[gph], 1.0f);
}

// ---------------- final: out = (pool/cnt) @ Wlin + blin ----------------------
__global__ void final_kernel(const float* __restrict__ Wlin,
                             const float* __restrict__ blin,
                             float* __restrict__ out) {
    int t = threadIdx.x;
    if (t >= NGRAPH * NCLS) return;
    int g = t / NCLS, j = t - g * NCLS;
    float inv = 1.f / fmaxf(g_cnt[g], 1.f);
    float s = 0.f;
    #pragma unroll
    for (int c = 0; c < 64; c++) s += g_pool[g * 64 + c] * Wlin[c * NCLS + j];
    out[t] = s * inv + blin[j];
}

// ---------------- launch ------------------------------------------------------
extern "C" void kernel_launch(void* const* d_in, const int* in_sizes, int n_in,
                              void* d_out, int out_size) {
    const float* x    = (const float*)d_in[0];
    const void*  ei   = d_in[1];
    const void*  bat  = d_in[2];
    const float* Wl1  = (const float*)d_in[3];
    const float* Wr1  = (const float*)d_in[4];
    const float* att1 = (const float*)d_in[5];
    const float* b1   = (const float*)d_in[6];
    const float* Wl2  = (const float*)d_in[7];
    const float* Wr2  = (const float*)d_in[8];
    const float* att2 = (const float*)d_in[9];
    const float* b2   = (const float*)d_in[10];
    const float* Wlin = (const float*)d_in[11];
    const float* blin = (const float*)d_in[12];
    float* out = (float*)d_out;

    int Nn = in_sizes[0] / 128;   // 50000
    int E  = in_sizes[1] / 2;     // 600000
    int ET = E + Nn;

    float *p_xlr1, *p_xlr2, *p_h1;
    cudaGetSymbolAddress((void**)&p_xlr1, g_xlr1);
    cudaGetSymbolAddress((void**)&p_xlr2, g_xlr2);
    cudaGetSymbolAddress((void**)&p_h1,   g_h1);

    detect_idx_kernel<<<1, 32>>>(ei);
    zero_all<<<( (long)Nn * 128 / 4 + 255) / 256, 256>>>();

    dim3 g1(4, (Nn + 63) / 64);
    gemm_dual<<<g1, 256>>>(x, Wl1, Wr1, p_xlr1, Nn, 128, 256);
    edge1_kernel<<<(int)(((long)ET * 32 + 255) / 256), 256>>>(ei, E, ET, att1);
    node1_kernel<<<(Nn * 32 + 255) / 256, 256>>>(b1, Nn);

    dim3 g2(2, (Nn + 63) / 64);
    gemm_dual<<<g2, 256>>>(p_h1, Wl2, Wr2, p_xlr2, Nn, 64, 128);
    edge2_kernel<<<(int)(((long)ET * 16 + 255) / 256), 256>>>(ei, E, ET, att2);
    node2_kernel<<<(Nn * 16 + 255) / 256, 256>>>(b2, bat, Nn);

    final_kernel<<<1, 640>>>(Wlin, blin, out);
}